// round 4
// baseline (speedup 1.0000x reference)
#include <cuda_runtime.h>
#include <math.h>

#define B      8
#define DM     4096
#define NH     32
#define NKV    8
#define HD     128
#define HID    14336
#define VOC    32000
#define SEQ    2048
#define POS_NEW 2047
#define NSPLIT 16            // attention kv splits

// All intermediate activation buffers are TRANSPOSED: [dim][batch=8].
__device__ float g_h   [DM*B];
__device__ float g_xn  [DM*B];
__device__ float g_q   [DM*B];
__device__ float g_k   [NKV*HD*B];
__device__ float g_v   [NKV*HD*B];
__device__ float g_pm  [B*NH*64];
__device__ float g_pl  [B*NH*64];
__device__ float g_pacc[B*NH*64*HD];
__device__ float g_ao  [DM*B];
__device__ float g_acc1[DM*B];
__device__ float g_res [DM*B];
__device__ float g_xn2 [DM*B];
__device__ float g_h1  [HID*B];
__device__ float g_h3  [HID*B];
__device__ float g_ffh [HID*B];
__device__ float g_acc2[DM*B];
__device__ float g_res2[DM*B];
__device__ float g_xn3 [DM*B];

// ---------------- zero atomic-accumulated buffers + output ----------------
__global__ void k_zero(float* __restrict__ out) {
    int i0 = blockIdx.x * blockDim.x + threadIdx.x;
    int st = gridDim.x * blockDim.x;
    for (int i = i0; i < B*VOC; i += st) out[i] = 0.f;
    for (int i = i0; i < DM*B; i += st) { g_q[i] = 0.f; g_acc1[i] = 0.f; g_acc2[i] = 0.f; }
    for (int i = i0; i < NKV*HD*B; i += st) { g_k[i] = 0.f; g_v[i] = 0.f; }
    for (int i = i0; i < HID*B; i += st) { g_h1[i] = 0.f; g_h3[i] = 0.f; }
}

// ---------------- embedding + rmsnorm1 (writes transposed) ----------------
__global__ void k_embed(const int* __restrict__ tokens,
                        const float* __restrict__ emb,
                        const float* __restrict__ gamma) {
    int b = blockIdx.x;
    int tok = tokens[b];
    __shared__ float red[256];
    float s = 0.f;
    for (int i = threadIdx.x; i < DM; i += 256) {
        float v = emb[(size_t)tok * DM + i];
        g_h[i*8 + b] = v;
        s += v * v;
    }
    red[threadIdx.x] = s; __syncthreads();
    for (int off = 128; off > 0; off >>= 1) {
        if (threadIdx.x < off) red[threadIdx.x] += red[threadIdx.x + off];
        __syncthreads();
    }
    float scale = 64.0f / sqrtf(red[0]);
    for (int i = threadIdx.x; i < DM; i += 256)
        g_xn[i*8 + b] = g_h[i*8 + b] * gamma[i] * scale;
}

// ---------------- residual add + rmsnorm (transposed buffers) ----------------
__global__ void k_addnorm(const float* __restrict__ acc,
                          const float* __restrict__ res,
                          const float* __restrict__ gamma,
                          float* __restrict__ outres,
                          float* __restrict__ outn) {
    int b = blockIdx.x;
    __shared__ float red[256];
    float s = 0.f;
    for (int i = threadIdx.x; i < DM; i += 256) {
        float t = acc[i*8 + b] + res[i*8 + b];
        outres[i*8 + b] = t;
        s += t * t;
    }
    red[threadIdx.x] = s; __syncthreads();
    for (int off = 128; off > 0; off >>= 1) {
        if (threadIdx.x < off) red[threadIdx.x] += red[threadIdx.x + off];
        __syncthreads();
    }
    float scale = 64.0f / sqrtf(red[0]);
    for (int i = threadIdx.x; i < DM; i += 256)
        outn[i*8 + b] = outres[i*8 + b] * gamma[i] * scale;
}

// =====================================================================
// GEMV v4: cp.async smem-ring pipeline.
// 512 threads (16 warps), 128 output cols/block, RPB rows per block.
// Stage = 16 rows x 128 cols (8KB). Thread t cp.asyncs the exact 16B it
// later consumes (row = warp id, cols = 4*lane) -> no barriers in loop.
// 8-slot ring, prefetch depth 6. f32x2 packed FMAs (batch pairs).
// Epilogue: per-warp STS.128 slices + tree reduce + atomicAdd.
// =====================================================================
__device__ __forceinline__ unsigned long long dup2(float w) {
    unsigned long long r;
    asm("mov.b64 %0, {%1, %1};" : "=l"(r) : "f"(w));
    return r;
}
__device__ __forceinline__ void fma2(unsigned long long& c, unsigned long long a,
                                     unsigned long long x) {
    asm("fma.rn.f32x2 %0, %1, %2, %0;" : "+l"(c) : "l"(a), "l"(x));
}
__device__ __forceinline__ float2 unpk(unsigned long long v) {
    float2 f;
    asm("mov.b64 {%0, %1}, %2;" : "=f"(f.x), "=f"(f.y) : "l"(v));
    return f;
}
__device__ __forceinline__ void cp16(unsigned int saddr, const void* gptr) {
    asm volatile("cp.async.cg.shared.global [%0], [%1], 16;" :: "r"(saddr), "l"(gptr));
}

#define GNSTAGE 8
#define GDEPTH  6

template<int RPB, bool TROUT>
__global__ void __launch_bounds__(512, 1)
k_gemv4(const float* __restrict__ X0, const float* __restrict__ W0, float* __restrict__ Y0,
        const float* __restrict__ X1, const float* __restrict__ W1, float* __restrict__ Y1,
        int K, int N) {
    constexpr int STG_TOT = RPB / 16;
    extern __shared__ float sm[];
    float* xs   = sm;                      // [RPB][8]
    float* ring = sm + RPB*8;              // GNSTAGE * 16 * 128 floats (64KB)
    float* sw   = ring + GNSTAGE*2048;     // [16][1024] (64KB)

    const float* X = blockIdx.z ? X1 : X0;
    const float* W = blockIdx.z ? W1 : W0;
    float*       Y = blockIdx.z ? Y1 : Y0;

    const int tid  = threadIdx.x;
    const int w    = tid >> 5, lane = tid & 31;
    const int k0   = blockIdx.y * RPB;
    const int nb   = blockIdx.x * 128;

    // stage x (transposed X -> contiguous copy)
    {
        const float4* src = (const float4*)(X + (size_t)k0 * 8);
        float4* dst = (float4*)xs;
        #pragma unroll
        for (int i = tid; i < RPB*2; i += 512) dst[i] = src[i];
    }

    unsigned int ring_sa = (unsigned int)__cvta_generic_to_shared(ring) + w*512 + lane*16;
    const char* gsrc = (const char*)(W + (size_t)(k0 + w) * N + nb + lane*4);
    const size_t gstep = (size_t)16 * N * 4;

    #pragma unroll
    for (int d = 0; d < GDEPTH; d++) {
        cp16(ring_sa + (d & (GNSTAGE-1))*8192, gsrc);
        gsrc += gstep;
        asm volatile("cp.async.commit_group;");
    }
    __syncthreads();   // xs visible

    unsigned long long acc[4][4];
    #pragma unroll
    for (int c = 0; c < 4; c++)
        #pragma unroll
        for (int p = 0; p < 4; p++) acc[c][p] = 0ull;

    #pragma unroll 8
    for (int s = 0; s < STG_TOT; s++) {
        if (s + GDEPTH < STG_TOT) {
            cp16(ring_sa + ((s + GDEPTH) & (GNSTAGE-1))*8192, gsrc);
            gsrc += gstep;
        }
        asm volatile("cp.async.commit_group;");
        asm volatile("cp.async.wait_group %0;" :: "n"(GDEPTH));

        const float4 wv = *(const float4*)((const char*)ring +
                              ((s & (GNSTAGE-1))*8192 + w*512 + lane*16));
        const float* xrow = xs + (s*16 + w)*8;
        ulonglong2 xa = *(const ulonglong2*)xrow;
        ulonglong2 xb = *(const ulonglong2*)(xrow + 4);
        unsigned long long xp0 = xa.x, xp1 = xa.y, xp2 = xb.x, xp3 = xb.y;
        unsigned long long wd0 = dup2(wv.x), wd1 = dup2(wv.y),
                           wd2 = dup2(wv.z), wd3 = dup2(wv.w);
        fma2(acc[0][0], wd0, xp0); fma2(acc[0][1], wd0, xp1);
        fma2(acc[0][2], wd0, xp2); fma2(acc[0][3], wd0, xp3);
        fma2(acc[1][0], wd1, xp0); fma2(acc[1][1], wd1, xp1);
        fma2(acc[1][2], wd1, xp2); fma2(acc[1][3], wd1, xp3);
        fma2(acc[2][0], wd2, xp0); fma2(acc[2][1], wd2, xp1);
        fma2(acc[2][2], wd2, xp2); fma2(acc[2][3], wd2, xp3);
        fma2(acc[3][0], wd3, xp0); fma2(acc[3][1], wd3, xp1);
        fma2(acc[3][2], wd3, xp2); fma2(acc[3][3], wd3, xp3);
    }

    // per-warp slice write (conflict-free STS.128)
    #pragma unroll
    for (int p = 0; p < 4; p++) {
        float2 c0 = unpk(acc[0][p]), c1 = unpk(acc[1][p]);
        float2 c2 = unpk(acc[2][p]), c3 = unpk(acc[3][p]);
        *(float4*)&sw[(w * 8 + 2*p    ) * 128 + lane * 4] = make_float4(c0.x, c1.x, c2.x, c3.x);
        *(float4*)&sw[(w * 8 + 2*p + 1) * 128 + lane * 4] = make_float4(c0.y, c1.y, c2.y, c3.y);
    }
    __syncthreads();

    #pragma unroll
    for (int o = tid; o < 1024; o += 512) {
        float ssum = 0.f;
        #pragma unroll
        for (int ww = 0; ww < 16; ww++) ssum += sw[ww * 1024 + o];
        int b = o >> 7, c = o & 127;
        if (TROUT) atomicAdd(&Y[(size_t)(nb + c)*8 + b], ssum);
        else       atomicAdd(&Y[(size_t)b*N + nb + c], ssum);
    }
}

// ---------------- RoPE on q and k (position = 2047, transposed) ----------------
__global__ void k_rope() {
    int idx = blockIdx.x * 256 + threadIdx.x;
    if (idx >= B*NH*64 + B*NKV*64) return;
    float* base;
    int j;
    if (idx < B*NH*64) {
        int b = idx / (NH*64); int r = idx % (NH*64);
        int h = r / 64; j = r % 64;
        base = &g_q[(h*HD + 2*j)*8 + b];
    } else {
        int t = idx - B*NH*64;
        int b = t / (NKV*64); int r = t % (NKV*64);
        int h = r / 64; j = r % 64;
        base = &g_k[(h*HD + 2*j)*8 + b];
    }
    float fe   = (float)(2 * j) * (1.0f / 128.0f);
    float invf = 1.0f / powf(10000.0f, fe);
    float ang  = 2047.0f * invf;
    float c = cosf(ang), s = sinf(ang);
    float x0 = base[0], x1 = base[8];
    base[0] = x0 * c - x1 * s;
    base[8] = x0 * s + x1 * c;
}

__device__ __forceinline__ float4 ld4t(const float* base, int d0, int b) {
    return make_float4(base[(d0+0)*8 + b], base[(d0+1)*8 + b],
                       base[(d0+2)*8 + b], base[(d0+3)*8 + b]);
}

// ---------------- attention: 16 splits, 4-position batched K/V loads ----------------
__global__ void __launch_bounds__(128)
k_attn(const float* __restrict__ ck, const float* __restrict__ cv) {
    int b = blockIdx.z, kv = blockIdx.y, split = blockIdx.x;
    int wid = threadIdx.x >> 5, lane = threadIdx.x & 31;
    int p0 = split * 128 + wid * 32;

    float4 q[4];
#pragma unroll
    for (int h = 0; h < 4; h++)
        q[h] = ld4t(g_q, (kv*4 + h)*HD + lane*4, b);

    float m[4], l[4];
    float4 a[4];
#pragma unroll
    for (int h = 0; h < 4; h++) { m[h] = -1e30f; l[h] = 0.f; a[h] = make_float4(0,0,0,0); }

    const float scale = 0.08838834764831845f;

    for (int pc = 0; pc < 32; pc += 4) {
        float4 kxs[4], vxs[4];
#pragma unroll
        for (int j = 0; j < 4; j++) {
            int p = p0 + pc + j;
            if (p == POS_NEW) kxs[j] = ld4t(g_k, kv*HD + lane*4, b);
            else kxs[j] = *(const float4*)&ck[(((size_t)b*SEQ + p)*NKV + kv)*HD + lane*4];
        }
#pragma unroll
        for (int j = 0; j < 4; j++) {
            int p = p0 + pc + j;
            if (p == POS_NEW) vxs[j] = ld4t(g_v, kv*HD + lane*4, b);
            else vxs[j] = *(const float4*)&cv[(((size_t)b*SEQ + p)*NKV + kv)*HD + lane*4];
        }
#pragma unroll
        for (int j = 0; j < 4; j++) {
            float4 kx = kxs[j];
            float s4[4];
#pragma unroll
            for (int h = 0; h < 4; h++)
                s4[h] = q[h].x*kx.x + q[h].y*kx.y + q[h].z*kx.z + q[h].w*kx.w;
#pragma unroll
            for (int off = 16; off; off >>= 1) {
#pragma unroll
                for (int h = 0; h < 4; h++)
                    s4[h] += __shfl_xor_sync(0xffffffffu, s4[h], off);
            }
            float4 vx = vxs[j];
#pragma unroll
            for (int h = 0; h < 4; h++) {
                float sc = s4[h] * scale;
                if (sc > m[h]) {
                    float corr = __expf(m[h] - sc);
                    l[h] *= corr;
                    a[h].x *= corr; a[h].y *= corr; a[h].z *= corr; a[h].w *= corr;
                    m[h] = sc;
                }
                float e = __expf(sc - m[h]);
                l[h] += e;
                a[h].x += e * vx.x; a[h].y += e * vx.y;
                a[h].z += e * vx.z; a[h].w += e * vx.w;
            }
        }
    }

    int part = split * 4 + wid;
#pragma unroll
    for (int h = 0; h < 4; h++) {
        int head = kv*4 + h;
        int pi = (b*NH + head)*64 + part;
        if (lane == 0) { g_pm[pi] = m[h]; g_pl[pi] = l[h]; }
        *(float4*)&g_pacc[(size_t)pi*HD + lane*4] = a[h];
    }
}

// ---------------- attention split combine (writes transposed g_ao) ----------------
__global__ void k_combine() {
    int bh = blockIdx.x;                 // b*NH + head
    int b = bh >> 5, head = bh & 31;
    int d = threadIdx.x;
    float M = -1e30f;
#pragma unroll
    for (int i = 0; i < 64; i++) M = fmaxf(M, g_pm[bh*64 + i]);
    float L = 0.f, o = 0.f;
#pragma unroll
    for (int i = 0; i < 64; i++) {
        float w = __expf(g_pm[bh*64 + i] - M);
        L += g_pl[bh*64 + i] * w;
        o += g_pacc[(size_t)(bh*64 + i)*HD + d] * w;
    }
    g_ao[(head*HD + d)*8 + b] = o / L;
}

// ---------------- silu(h1) * h3 (elementwise, layout-agnostic) ----------------
__global__ void k_silu() {
    int i = blockIdx.x * 256 + threadIdx.x;
    if (i < B*HID) {
        float x = g_h1[i];
        g_ffh[i] = (x / (1.0f + expf(-x))) * g_h3[i];
    }
}

// ---------------- launch ----------------
static inline int smem4(int rpb) { return (rpb*8 + GNSTAGE*2048 + 16*1024) * (int)sizeof(float); }

extern "C" void kernel_launch(void* const* d_in, const int* in_sizes, int n_in,
                              void* d_out, int out_size) {
    const int*   tokens = (const int*)  d_in[0];
    const float* emb  = (const float*)d_in[2];
    const float* g1   = (const float*)d_in[3];
    const float* g2   = (const float*)d_in[4];
    const float* gf   = (const float*)d_in[5];
    const float* wq   = (const float*)d_in[6];
    const float* wk   = (const float*)d_in[7];
    const float* wv   = (const float*)d_in[8];
    const float* wo   = (const float*)d_in[9];
    const float* w1   = (const float*)d_in[10];
    const float* w2   = (const float*)d_in[11];
    const float* w3   = (const float*)d_in[12];
    const float* wout = (const float*)d_in[13];
    const float* ck   = (const float*)d_in[14];
    const float* cv   = (const float*)d_in[15];
    float* out = (float*)d_out;

    float *p_xn, *p_q, *p_k, *p_v, *p_ao, *p_acc1, *p_h, *p_res, *p_xn2;
    float *p_h1, *p_h3, *p_ffh, *p_acc2, *p_res2, *p_xn3;
    cudaGetSymbolAddress((void**)&p_xn,  g_xn);
    cudaGetSymbolAddress((void**)&p_q,   g_q);
    cudaGetSymbolAddress((void**)&p_k,   g_k);
    cudaGetSymbolAddress((void**)&p_v,   g_v);
    cudaGetSymbolAddress((void**)&p_ao,  g_ao);
    cudaGetSymbolAddress((void**)&p_acc1,g_acc1);
    cudaGetSymbolAddress((void**)&p_h,   g_h);
    cudaGetSymbolAddress((void**)&p_res, g_res);
    cudaGetSymbolAddress((void**)&p_xn2, g_xn2);
    cudaGetSymbolAddress((void**)&p_h1,  g_h1);
    cudaGetSymbolAddress((void**)&p_h3,  g_h3);
    cudaGetSymbolAddress((void**)&p_ffh, g_ffh);
    cudaGetSymbolAddress((void**)&p_acc2,g_acc2);
    cudaGetSymbolAddress((void**)&p_res2,g_res2);
    cudaGetSymbolAddress((void**)&p_xn3, g_xn3);

    cudaFuncSetAttribute(k_gemv4<256, true >, cudaFuncAttributeMaxDynamicSharedMemorySize, smem4(256));
    cudaFuncSetAttribute(k_gemv4<512, true >, cudaFuncAttributeMaxDynamicSharedMemorySize, smem4(512));
    cudaFuncSetAttribute(k_gemv4<512, false>, cudaFuncAttributeMaxDynamicSharedMemorySize, smem4(512));

    k_zero<<<256, 256>>>(out);
    k_embed<<<8, 256>>>(tokens, emb, g1);

    // QKV
    k_gemv4<256, true><<<dim3(32, 16, 1), 512, smem4(256)>>>(p_xn, wq, p_q, p_xn, wq, p_q, DM, DM);
    k_gemv4<256, true><<<dim3(8, 16, 2),  512, smem4(256)>>>(p_xn, wk, p_k, p_xn, wv, p_v, DM, NKV*HD);

    k_rope<<<80, 256>>>();
    k_attn<<<dim3(NSPLIT, 8, 8), 128>>>(ck, cv);
    k_combine<<<B*NH, 128>>>();

    // wo + residual/norm
    k_gemv4<256, true><<<dim3(32, 16, 1), 512, smem4(256)>>>(p_ao, wo, p_acc1, p_ao, wo, p_acc1, DM, DM);
    k_addnorm<<<8, 256>>>(p_acc1, p_h, g2, p_res, p_xn2);

    // FFN
    k_gemv4<512, true><<<dim3(112, 8, 2), 512, smem4(512)>>>(p_xn2, w1, p_h1, p_xn2, w3, p_h3, DM, HID);
    k_silu<<<(B*HID + 255)/256, 256>>>();
    k_gemv4<512, true><<<dim3(32, 28, 1), 512, smem4(512)>>>(p_ffh, w2, p_acc2, p_ffh, w2, p_acc2, HID, DM);
    k_addnorm<<<8, 256>>>(p_acc2, p_res, gf, p_res2, p_xn3);

    // logits (untransposed output, 8 K-splits)
    k_gemv4<512, false><<<dim3(250, 8, 1), 512, smem4(512)>>>(p_xn3, wout, out, p_xn3, wout, out, DM, VOC);
}